// round 6
// baseline (speedup 1.0000x reference)
#include <cuda_runtime.h>

// Problem constants
#define T_    256
#define B_    256
#define H_    1024
#define E_    300
#define FEAT  319
#define FEATP 320
#define C_    13
#define G4H   4096
#define M_    (T_ * B_)

#define SCAN_NCTA 128
// Ws[4][1024][8] fp32 (131072 B) + Hs[4][256][20] fp32 (81920 B)
#define SCAN_SMEM (131072 + 81920)
// lstm1: 3 stages x (A[256][36] + B[128][36]) fp32
#define L1_STAGE_FLOATS (256 * 36 + 128 * 36)
#define L1_SMEM (3 * L1_STAGE_FLOATS * 4)

// -------- scratch (static device globals; no allocation anywhere) --------
__device__ float g_X[(size_t)M_ * FEATP];
__device__ float g_wi0p[(size_t)G4H * FEATP];
__device__ float g_pre0[(size_t)M_ * G4H];
__device__ float g_h0[(size_t)M_ * H_];
__device__ float g_c0[(size_t)M_ * H_];
__device__ float g_h1[(size_t)M_ * H_];
__device__ unsigned g_bar;

__device__ __forceinline__ float sigmoidf_(float x) {
    return 1.0f / (1.0f + __expf(-x));
}
// D += A(16x8,row) * B(8x8,col); fp32 bits fed to tf32 MMA (HW truncates mantissa)
__device__ __forceinline__ void mma8(float* d, const unsigned* a, const unsigned* b) {
    asm volatile(
        "mma.sync.aligned.m16n8k8.row.col.f32.tf32.tf32.f32 "
        "{%0,%1,%2,%3}, {%4,%5,%6,%7}, {%8,%9}, {%0,%1,%2,%3};\n"
        : "+f"(d[0]), "+f"(d[1]), "+f"(d[2]), "+f"(d[3])
        : "r"(a[0]), "r"(a[1]), "r"(a[2]), "r"(a[3]), "r"(b[0]), "r"(b[1]));
}
__device__ __forceinline__ void cpa16(void* sdst, const void* gsrc) {
    unsigned s = (unsigned)__cvta_generic_to_shared(sdst);
    asm volatile("cp.async.cg.shared.global [%0], [%1], 16;\n" :: "r"(s), "l"(gsrc));
}
#define CP_COMMIT() asm volatile("cp.async.commit_group;\n" ::: "memory")
template <int N> __device__ __forceinline__ void cp_wait() {
    asm volatile("cp.async.wait_group %0;\n" :: "n"(N) : "memory");
}

__global__ void k_reset() { g_bar = 0u; }

// ===========================================================================
// Kernel 1: build X = [emb_table[tokens] | casing | pos | 0pad]
// ===========================================================================
__global__ void k_build_x(const int* __restrict__ tokens,
                          const float* __restrict__ casing,
                          const float* __restrict__ pos,
                          const float* __restrict__ emb) {
    int m = blockIdx.x;
    int tok = tokens[m];
    const float* erow = emb + (size_t)tok * E_;
    float* xrow = g_X + (size_t)m * FEATP;
    for (int k = threadIdx.x; k < FEATP; k += blockDim.x) {
        float v;
        if (k < E_)            v = erow[k];
        else if (k < E_ + 7)   v = casing[m * 7 + (k - E_)];
        else if (k < FEAT)     v = pos[m * 12 + (k - E_ - 7)];
        else                   v = 0.0f;
        xrow[k] = v;
    }
}

// ===========================================================================
// Kernel 2: pad wi0 [4096,319] -> [4096,320]
// ===========================================================================
__global__ void k_pad_wi0(const float* __restrict__ wi0) {
    int j = blockIdx.x;
    for (int k = threadIdx.x; k < FEATP; k += blockDim.x)
        g_wi0p[(size_t)j * FEATP + k] = (k < FEAT) ? wi0[(size_t)j * FEAT + k] : 0.0f;
}

// ===========================================================================
// Kernel 3: pre0 = X @ wi0p^T + (bi0+bh0)   [65536 x 4096], K=320
// ===========================================================================
__global__ __launch_bounds__(256) void k_gemm_pre0(const float* __restrict__ bi0,
                                                   const float* __restrict__ bh0) {
    __shared__ unsigned As[32][136];
    __shared__ unsigned Bs[32][136];

    const int m0 = blockIdx.y * 128;
    const int n0 = blockIdx.x * 128;
    const int tid = threadIdx.x, lane = tid & 31, wid = tid >> 5;
    const int wm = wid & 1, wn = wid >> 1;
    const int tg = lane & 3, gr = lane >> 2;

    float acc[4][4][4];
#pragma unroll
    for (int i = 0; i < 4; i++)
#pragma unroll
        for (int j = 0; j < 4; j++)
#pragma unroll
            for (int r = 0; r < 4; r++) acc[i][j][r] = 0.0f;

    float4 pa[4], pb[4];
    auto loadA = [&](int kc) {
#pragma unroll
        for (int it = 0; it < 4; it++) {
            int idx = tid + it * 256, mm = idx & 127, kq = idx >> 7;
            pa[it] = *(const float4*)(g_X + (size_t)(m0 + mm) * FEATP + kc * 32 + kq * 4);
        }
    };
    auto loadB = [&](int kc) {
#pragma unroll
        for (int it = 0; it < 4; it++) {
            int idx = tid + it * 256, nn = idx & 127, kq = idx >> 7;
            pb[it] = *(const float4*)(g_wi0p + (size_t)(n0 + nn) * FEATP + kc * 32 + kq * 4);
        }
    };
    auto stash = [&]() {
#pragma unroll
        for (int it = 0; it < 4; it++) {
            int idx = tid + it * 256, mm = idx & 127, kq = idx >> 7;
            As[kq * 4 + 0][mm] = __float_as_uint(pa[it].x);
            As[kq * 4 + 1][mm] = __float_as_uint(pa[it].y);
            As[kq * 4 + 2][mm] = __float_as_uint(pa[it].z);
            As[kq * 4 + 3][mm] = __float_as_uint(pa[it].w);
        }
#pragma unroll
        for (int it = 0; it < 4; it++) {
            int idx = tid + it * 256, nn = idx & 127, kq = idx >> 7;
            Bs[kq * 4 + 0][nn] = __float_as_uint(pb[it].x);
            Bs[kq * 4 + 1][nn] = __float_as_uint(pb[it].y);
            Bs[kq * 4 + 2][nn] = __float_as_uint(pb[it].z);
            Bs[kq * 4 + 3][nn] = __float_as_uint(pb[it].w);
        }
    };

    loadA(0); loadB(0);
    for (int kc = 0; kc < FEATP / 32; kc++) {
        __syncthreads();
        stash();
        __syncthreads();
        if (kc + 1 < FEATP / 32) { loadA(kc + 1); loadB(kc + 1); }
#pragma unroll
        for (int ks = 0; ks < 4; ks++) {
            const int k8 = ks * 8;
            unsigned a[4][4], b[4][2];
#pragma unroll
            for (int mt = 0; mt < 4; mt++) {
                int mb = wm * 64 + mt * 16;
                a[mt][0] = As[k8 + tg][mb + gr];
                a[mt][1] = As[k8 + tg][mb + 8 + gr];
                a[mt][2] = As[k8 + 4 + tg][mb + gr];
                a[mt][3] = As[k8 + 4 + tg][mb + 8 + gr];
            }
#pragma unroll
            for (int nt = 0; nt < 4; nt++) {
                int nb = wn * 32 + nt * 8;
                b[nt][0] = Bs[k8 + tg][nb + gr];
                b[nt][1] = Bs[k8 + 4 + tg][nb + gr];
            }
#pragma unroll
            for (int mt = 0; mt < 4; mt++)
#pragma unroll
                for (int nt = 0; nt < 4; nt++) mma8(acc[mt][nt], a[mt], b[nt]);
        }
    }

#pragma unroll
    for (int nt = 0; nt < 4; nt++) {
        int n = n0 + wn * 32 + nt * 8 + 2 * tg;
        float b0 = bi0[n] + bh0[n];
        float b1 = bi0[n + 1] + bh0[n + 1];
#pragma unroll
        for (int mt = 0; mt < 4; mt++) {
            int m = m0 + wm * 64 + mt * 16 + gr;
            float2 v0 = make_float2(acc[mt][nt][0] + b0, acc[mt][nt][1] + b1);
            float2 v1 = make_float2(acc[mt][nt][2] + b0, acc[mt][nt][3] + b1);
            *(float2*)(g_pre0 + (size_t)m * G4H + n) = v0;
            *(float2*)(g_pre0 + (size_t)(m + 8) * G4H + n) = v1;
        }
    }
}

// ===========================================================================
// Kernel 4: PERSISTENT layer-0 scan; 512 threads (16 warps, 16 rows/warp).
// 4-stage cp.async pipeline (k=16 chunks). CTA nb owns cols [nb*8,nb*8+8)/gate.
// ===========================================================================
__global__ __launch_bounds__(512, 1) void k_lstm0_scan(
    const float* __restrict__ h_init0, const float* __restrict__ c_init0,
    const float* __restrict__ wh0) {
    extern __shared__ float smx[];
    float* Ws = smx;                     // [4][1024][8]  g*8192 + k*8 + n
    float* Hs = smx + 4 * 1024 * 8;      // [4][256][20]  stage*5120 + m*20 + k

    const int tid = threadIdx.x, lane = tid & 31, wid = tid >> 5;  // wid 0..15
    const int tg = lane & 3, gr = lane >> 2;
    const int n0 = blockIdx.x * 8;
    const int mb = wid * 16;

    // ---- one-time: weight slab -> SMEM ----
#pragma unroll
    for (int rr = 0; rr < 2; rr++) {
        int r = wid * 2 + rr;                // 0..31 = g*8 + n
        int g = r >> 3, n = r & 7;
        const float* src = wh0 + (size_t)(g * H_ + n0 + n) * H_;
        float* dst = Ws + g * 8192 + n;
        for (int k4 = lane; k4 < 256; k4 += 32) {
            float4 v = *(const float4*)(src + k4 * 4);
            dst[(k4 * 4 + 0) * 8] = v.x;
            dst[(k4 * 4 + 1) * 8] = v.y;
            dst[(k4 * 4 + 2) * 8] = v.z;
            dst[(k4 * 4 + 3) * 8] = v.w;
        }
    }

    // ---- c state in registers ----
    float creg[2][2];
#pragma unroll
    for (int hf = 0; hf < 2; hf++) {
        int m = mb + hf * 8 + gr;
        float2 cv = *(const float2*)(c_init0 + (size_t)m * H_ + n0 + 2 * tg);
        creg[hf][0] = cv.x;
        creg[hf][1] = cv.y;
    }

    float acc[4][4];
#pragma unroll
    for (int g = 0; g < 4; g++)
#pragma unroll
        for (int r = 0; r < 4; r++) acc[g][r] = 0.0f;

    __syncthreads();   // weights visible

    const int row_f = tid >> 2, q_f = tid & 3;   // fill: rows 0..127 (+128), q 0..3

    for (int t = 0; t < T_; t++) {
        const float* hprev = (t == 0) ? h_init0 : (g_h0 + (size_t)(t - 1) * B_ * H_);
        float* hout = g_h0 + (size_t)t * B_ * H_;
        float* cout = g_c0 + (size_t)t * B_ * H_;
        const float* pt = g_pre0 + (size_t)t * B_ * G4H;

        auto fill = [&](int kc) {
            float* dst = Hs + (kc & 3) * 5120;
#pragma unroll
            for (int it = 0; it < 2; it++) {
                int row = row_f + it * 128;
                cpa16(dst + row * 20 + q_f * 4,
                      hprev + (size_t)row * H_ + kc * 16 + q_f * 4);
            }
        };

        fill(0); CP_COMMIT();
        fill(1); CP_COMMIT();
        fill(2); CP_COMMIT();

        for (int kc = 0; kc < 64; kc++) {
            cp_wait<2>();
            __syncthreads();
            const float* Hb = Hs + (kc & 3) * 5120;
#pragma unroll
            for (int ks = 0; ks < 2; ks++) {
                const int k8 = ks * 8;
                unsigned a[4];
                {
                    const float* r0 = Hb + (mb + gr) * 20;
                    const float* r1 = r0 + 8 * 20;
                    a[0] = __float_as_uint(r0[k8 + tg]);
                    a[1] = __float_as_uint(r1[k8 + tg]);
                    a[2] = __float_as_uint(r0[k8 + 4 + tg]);
                    a[3] = __float_as_uint(r1[k8 + 4 + tg]);
                }
#pragma unroll
                for (int g = 0; g < 4; g++) {
                    const float* wg = Ws + g * 8192 + (kc * 16 + k8) * 8;
                    unsigned bb[2];
                    bb[0] = __float_as_uint(wg[tg * 8 + gr]);
                    bb[1] = __float_as_uint(wg[(4 + tg) * 8 + gr]);
                    mma8(acc[g], a, bb);
                }
            }
            if (kc + 3 < 64) fill(kc + 3);
            CP_COMMIT();
        }

        // ---- fused gate epilogue; c stays in registers ----
#pragma unroll
        for (int hf = 0; hf < 2; hf++) {
            int m = mb + hf * 8 + gr;
            const float* p = pt + (size_t)m * G4H + n0 + 2 * tg;
            float2 Pi = *(const float2*)(p);
            float2 Pf = *(const float2*)(p + H_);
            float2 Po = *(const float2*)(p + 2 * H_);
            float2 Pg = *(const float2*)(p + 3 * H_);
            float h2[2];
#pragma unroll
            for (int cc = 0; cc < 2; cc++) {
                int r = hf * 2 + cc;
                float pi = acc[0][r] + (cc ? Pi.y : Pi.x);
                float pfv = acc[1][r] + (cc ? Pf.y : Pf.x);
                float po = acc[2][r] + (cc ? Po.y : Po.x);
                float pg = acc[3][r] + (cc ? Pg.y : Pg.x);
                float c = sigmoidf_(pfv) * creg[hf][cc] + sigmoidf_(pi) * tanhf(pg);
                creg[hf][cc] = c;
                h2[cc] = sigmoidf_(po) * tanhf(c);
            }
            *(float2*)(hout + (size_t)m * H_ + n0 + 2 * tg) = make_float2(h2[0], h2[1]);
            *(float2*)(cout + (size_t)m * H_ + n0 + 2 * tg) =
                make_float2(creg[hf][0], creg[hf][1]);
        }
#pragma unroll
        for (int g = 0; g < 4; g++)
#pragma unroll
            for (int r = 0; r < 4; r++) acc[g][r] = 0.0f;

        // ---- inter-CTA barrier ----
        __syncthreads();
        if (tid == 0) {
            __threadfence();
            atomicAdd(&g_bar, 1u);
            unsigned tgt = (unsigned)(t + 1) * SCAN_NCTA;
            while (atomicAdd(&g_bar, 0u) < tgt) __nanosleep(64);
            __threadfence();
        }
        __syncthreads();
    }
}

// ===========================================================================
// Kernel 5: layer-1 batch-parallel; BM=256, 32 cols/gate; 512 threads
// (16 warps: 8M x 2N), 3-stage cp.async, K=2048. Grid 32 x 256.
// ===========================================================================
__global__ __launch_bounds__(512, 1) void k_lstm1(const float* __restrict__ wi1,
                                                  const float* __restrict__ wh1,
                                                  const float* __restrict__ bi1,
                                                  const float* __restrict__ bh1) {
    extern __shared__ float sm1[];
    // stage s: A at sm1 + s*L1_STAGE_FLOATS ([256][36]), B at +9216 ([128][36])

    const int m0 = blockIdx.y * 256;
    const int n0 = blockIdx.x * 32;
    const int tid = threadIdx.x, lane = tid & 31, wid = tid >> 5;
    const int wm = wid & 7, wn = wid >> 3;
    const int tg = lane & 3, gr = lane >> 2;

    float acc[4][2][2][4];
#pragma unroll
    for (int g = 0; g < 4; g++)
#pragma unroll
        for (int mt = 0; mt < 2; mt++)
#pragma unroll
            for (int nt = 0; nt < 2; nt++)
#pragma unroll
                for (int r = 0; r < 4; r++) acc[g][mt][nt][r] = 0.0f;

    auto fill = [&](int kc) {
        int s = kc % 3;
        bool second = (kc >= 32);
        int kk0 = (kc * 32) & (H_ - 1);
        float* dA = sm1 + s * L1_STAGE_FLOATS;
#pragma unroll
        for (int it = 0; it < 4; it++) {
            int idx = tid + it * 512, row = idx >> 3, q = idx & 7;   // row 0..255
            int m = m0 + row, bq = m & 255;
            int msel = second ? (m - bq + 255 - bq) : m;
            cpa16(dA + row * 36 + q * 4, g_h0 + (size_t)msel * H_ + kk0 + q * 4);
        }
        const float* W = second ? wh1 : wi1;
        float* dB = dA + 256 * 36;
#pragma unroll
        for (int it = 0; it < 2; it++) {
            int idx = tid + it * 512, row = idx >> 3, q = idx & 7;   // row 0..127
            int g = row >> 5, nn = row & 31;
            cpa16(dB + row * 36 + q * 4,
                  W + (size_t)(g * H_ + n0 + nn) * H_ + kk0 + q * 4);
        }
    };

    fill(0); CP_COMMIT();
    fill(1); CP_COMMIT();

    for (int kc = 0; kc < 64; kc++) {
        cp_wait<1>();
        __syncthreads();
        const float* Ab = sm1 + (kc % 3) * L1_STAGE_FLOATS;
        const float* Bb = Ab + 256 * 36;
#pragma unroll
        for (int ks = 0; ks < 4; ks++) {
            const int k8 = ks * 8;
            unsigned a[2][4];
#pragma unroll
            for (int mt = 0; mt < 2; mt++) {
                const float* r0 = Ab + (wm * 32 + mt * 16 + gr) * 36;
                const float* r1 = r0 + 8 * 36;
                a[mt][0] = __float_as_uint(r0[k8 + tg]);
                a[mt][1] = __float_as_uint(r1[k8 + tg]);
                a[mt][2] = __float_as_uint(r0[k8 + 4 + tg]);
                a[mt][3] = __float_as_uint(r1[k8 + 4 + tg]);
            }
#pragma unroll
            for (int g = 0; g < 4; g++) {
#pragma unroll
                for (int nt = 0; nt < 2; nt++) {
                    const float* rb = Bb + (g * 32 + wn * 16 + nt * 8 + gr) * 36;
                    unsigned b[2];
                    b[0] = __float_as_uint(rb[k8 + tg]);
                    b[1] = __float_as_uint(rb[k8 + 4 + tg]);
                    mma8(acc[g][0][nt], a[0], b);
                    mma8(acc[g][1][nt], a[1], b);
                }
            }
        }
        if (kc + 2 < 64) fill(kc + 2);
        CP_COMMIT();
    }

#pragma unroll
    for (int mt = 0; mt < 2; mt++)
#pragma unroll
        for (int half = 0; half < 2; half++) {
            int m = m0 + wm * 32 + mt * 16 + half * 8 + gr;
            int bq = m & 255;
            int mflip = m - bq + 255 - bq;
            const float* cp = g_c0 + (size_t)mflip * H_;
            float* hp = g_h1 + (size_t)m * H_;
#pragma unroll
            for (int nt = 0; nt < 2; nt++)
#pragma unroll
                for (int cc = 0; cc < 2; cc++) {
                    int nn = n0 + wn * 16 + nt * 8 + 2 * tg + cc;
                    int r = half * 2 + cc;
                    float pi = acc[0][mt][nt][r] + bi1[nn] + bh1[nn];
                    float pf = acc[1][mt][nt][r] + bi1[H_ + nn] + bh1[H_ + nn];
                    float po = acc[2][mt][nt][r] + bi1[2 * H_ + nn] + bh1[2 * H_ + nn];
                    float pg = acc[3][mt][nt][r] + bi1[3 * H_ + nn] + bh1[3 * H_ + nn];
                    float c = sigmoidf_(pf) * cp[nn] + sigmoidf_(pi) * tanhf(pg);
                    hp[nn] = sigmoidf_(po) * tanhf(c);
                }
        }
}

// ===========================================================================
// Kernel 6: decode. out[m, c] = [h0[m] | h1[m]] . dec_w[c] + dec_b[c]
// ===========================================================================
__global__ __launch_bounds__(256) void k_decode(const float* __restrict__ dec_w,
                                                const float* __restrict__ dec_b,
                                                float* __restrict__ out) {
    int gwarp = (blockIdx.x * blockDim.x + threadIdx.x) >> 5;
    int lane = threadIdx.x & 31;
    if (gwarp >= M_) return;
    const float* h0r = g_h0 + (size_t)gwarp * H_;
    const float* h1r = g_h1 + (size_t)gwarp * H_;

    float acc[C_];
#pragma unroll
    for (int c = 0; c < C_; c++) acc[c] = 0.0f;

    for (int k = lane * 4; k < H_; k += 128) {
        float4 v0 = *(const float4*)(h0r + k);
        float4 v1 = *(const float4*)(h1r + k);
#pragma unroll
        for (int c = 0; c < C_; c++) {
            const float* w = dec_w + (size_t)c * 2 * H_;
            float4 w0 = *(const float4*)(w + k);
            float4 w1 = *(const float4*)(w + H_ + k);
            acc[c] += v0.x * w0.x + v0.y * w0.y + v0.z * w0.z + v0.w * w0.w
                    + v1.x * w1.x + v1.y * w1.y + v1.z * w1.z + v1.w * w1.w;
        }
    }
#pragma unroll
    for (int c = 0; c < C_; c++) {
#pragma unroll
        for (int off = 16; off > 0; off >>= 1)
            acc[c] += __shfl_down_sync(0xFFFFFFFFu, acc[c], off);
    }
    if (lane == 0) {
#pragma unroll
        for (int c = 0; c < C_; c++)
            out[(size_t)gwarp * C_ + c] = acc[c] + dec_b[c];
    }
}

// ===========================================================================
// Launch
// ===========================================================================
extern "C" void kernel_launch(void* const* d_in, const int* in_sizes, int n_in,
                              void* d_out, int out_size) {
    const int*   tokens = (const int*)d_in[0];
    const float* casing = (const float*)d_in[1];
    const float* pos    = (const float*)d_in[2];
    const float* emb    = (const float*)d_in[3];
    const float* wi0    = (const float*)d_in[4];
    const float* bi0    = (const float*)d_in[5];
    const float* wh0    = (const float*)d_in[6];
    const float* bh0    = (const float*)d_in[7];
    const float* wi1    = (const float*)d_in[8];
    const float* bi1    = (const float*)d_in[9];
    const float* wh1    = (const float*)d_in[10];
    const float* bh1    = (const float*)d_in[11];
    const float* dec_w  = (const float*)d_in[12];
    const float* dec_b  = (const float*)d_in[13];
    const float* h_init = (const float*)d_in[14];
    const float* c_init = (const float*)d_in[15];
    float* out = (float*)d_out;

    (void)in_sizes; (void)n_in; (void)out_size;

    cudaFuncSetAttribute(k_lstm0_scan, cudaFuncAttributeMaxDynamicSharedMemorySize,
                         SCAN_SMEM);
    cudaFuncSetAttribute(k_lstm1, cudaFuncAttributeMaxDynamicSharedMemorySize,
                         L1_SMEM);

    k_reset<<<1, 1>>>();
    k_build_x<<<M_, 256>>>(tokens, casing, pos, emb);
    k_pad_wi0<<<G4H, 256>>>(wi0);
    k_gemm_pre0<<<dim3(G4H / 128, M_ / 128), 256>>>(bi0, bh0);
    k_lstm0_scan<<<SCAN_NCTA, 512, SCAN_SMEM>>>(h_init, c_init, wh0);
    k_lstm1<<<dim3(H_ / 32, M_ / 256), 512, L1_SMEM>>>(wi1, wh1, bi1, bh1);
    k_decode<<<(M_ * 32) / 256, 256>>>(dec_w, dec_b, out);
}

// round 7
// speedup vs baseline: 1.0541x; 1.0541x over previous
#include <cuda_runtime.h>

// Problem constants
#define T_    256
#define B_    256
#define H_    1024
#define E_    300
#define FEAT  319
#define FEATP 320
#define C_    13
#define G4H   4096
#define M_    (T_ * B_)

#define SCAN_NCTA 128
// Ws[4][1024][8] fp32 (131072 B) + Hs[4][256][20] fp32 (81920 B)
#define SCAN_SMEM (131072 + 81920)
// lstm1: 3 stages x (A[128][36] + B[256][36]) fp32 = 165888 B
#define L1_STAGE_FLOATS (128 * 36 + 256 * 36)
#define L1_SMEM (3 * L1_STAGE_FLOATS * 4)
// pre0: 3 stages x (A[256][36] + B[128][36]) fp32 = 165888 B
#define P0_STAGE_FLOATS (256 * 36 + 128 * 36)
#define P0_SMEM (3 * P0_STAGE_FLOATS * 4)

// -------- scratch (static device globals; no allocation anywhere) --------
__device__ float g_X[(size_t)M_ * FEATP];
__device__ float g_wi0p[(size_t)G4H * FEATP];
__device__ float g_pre0[(size_t)M_ * G4H];
__device__ float g_h0[(size_t)M_ * H_];
__device__ float g_c0[(size_t)M_ * H_];
__device__ float g_h1[(size_t)M_ * H_];
__device__ unsigned g_bar;

__device__ __forceinline__ float sigmoidf_(float x) {
    return 1.0f / (1.0f + __expf(-x));
}
// D += A(16x8,row) * B(8x8,col); fp32 bits fed to tf32 MMA (HW truncates mantissa)
__device__ __forceinline__ void mma8(float* d, const unsigned* a, const unsigned* b) {
    asm volatile(
        "mma.sync.aligned.m16n8k8.row.col.f32.tf32.tf32.f32 "
        "{%0,%1,%2,%3}, {%4,%5,%6,%7}, {%8,%9}, {%0,%1,%2,%3};\n"
        : "+f"(d[0]), "+f"(d[1]), "+f"(d[2]), "+f"(d[3])
        : "r"(a[0]), "r"(a[1]), "r"(a[2]), "r"(a[3]), "r"(b[0]), "r"(b[1]));
}
__device__ __forceinline__ void cpa16(void* sdst, const void* gsrc) {
    unsigned s = (unsigned)__cvta_generic_to_shared(sdst);
    asm volatile("cp.async.cg.shared.global [%0], [%1], 16;\n" :: "r"(s), "l"(gsrc));
}
#define CP_COMMIT() asm volatile("cp.async.commit_group;\n" ::: "memory")
template <int N> __device__ __forceinline__ void cp_wait() {
    asm volatile("cp.async.wait_group %0;\n" :: "n"(N) : "memory");
}

__global__ void k_reset() { g_bar = 0u; }

// ===========================================================================
// Kernel 1: build X = [emb_table[tokens] | casing | pos | 0pad]
// ===========================================================================
__global__ void k_build_x(const int* __restrict__ tokens,
                          const float* __restrict__ casing,
                          const float* __restrict__ pos,
                          const float* __restrict__ emb) {
    int m = blockIdx.x;
    int tok = tokens[m];
    const float* erow = emb + (size_t)tok * E_;
    float* xrow = g_X + (size_t)m * FEATP;
    for (int k = threadIdx.x; k < FEATP; k += blockDim.x) {
        float v;
        if (k < E_)            v = erow[k];
        else if (k < E_ + 7)   v = casing[m * 7 + (k - E_)];
        else if (k < FEAT)     v = pos[m * 12 + (k - E_ - 7)];
        else                   v = 0.0f;
        xrow[k] = v;
    }
}

// ===========================================================================
// Kernel 2: pad wi0 [4096,319] -> [4096,320]
// ===========================================================================
__global__ void k_pad_wi0(const float* __restrict__ wi0) {
    int j = blockIdx.x;
    for (int k = threadIdx.x; k < FEATP; k += blockDim.x)
        g_wi0p[(size_t)j * FEATP + k] = (k < FEAT) ? wi0[(size_t)j * FEAT + k] : 0.0f;
}

// ===========================================================================
// Kernel 3: pre0 = X @ wi0p^T + (bi0+bh0)   [65536 x 4096], K=320 (10 chunks)
// BM=256, BN=128; 8 warps WM=4 x WN=2; per-warp mt=4, nt=8; acc=128 regs.
// 3-stage cp.async. LDS 128KB per 512 mma (ratio 0.25).
// ===========================================================================
__global__ __launch_bounds__(256, 1) void k_gemm_pre0(const float* __restrict__ bi0,
                                                      const float* __restrict__ bh0) {
    extern __shared__ float smp[];
    // stage s: A [256][36] at smp + s*P0_STAGE_FLOATS, B [128][36] at +256*36

    const int m0 = blockIdx.y * 256;
    const int n0 = blockIdx.x * 128;
    const int tid = threadIdx.x, lane = tid & 31, wid = tid >> 5;
    const int wm = wid & 3, wn = wid >> 2;          // WM=4, WN=2
    const int tg = lane & 3, gr = lane >> 2;

    float acc[4][8][4];
#pragma unroll
    for (int mt = 0; mt < 4; mt++)
#pragma unroll
        for (int nt = 0; nt < 8; nt++)
#pragma unroll
            for (int r = 0; r < 4; r++) acc[mt][nt][r] = 0.0f;

    auto fill = [&](int kc) {
        int s = kc % 3;
        float* dA = smp + s * P0_STAGE_FLOATS;
#pragma unroll
        for (int it = 0; it < 8; it++) {
            int idx = tid + it * 256, row = idx >> 3, q = idx & 7;   // row 0..255
            cpa16(dA + row * 36 + q * 4,
                  g_X + (size_t)(m0 + row) * FEATP + kc * 32 + q * 4);
        }
        float* dB = dA + 256 * 36;
#pragma unroll
        for (int it = 0; it < 4; it++) {
            int idx = tid + it * 256, row = idx >> 3, q = idx & 7;   // row 0..127
            cpa16(dB + row * 36 + q * 4,
                  g_wi0p + (size_t)(n0 + row) * FEATP + kc * 32 + q * 4);
        }
    };

    fill(0); CP_COMMIT();
    fill(1); CP_COMMIT();

    for (int kc = 0; kc < 10; kc++) {
        cp_wait<1>();
        __syncthreads();
        const float* Ab = smp + (kc % 3) * P0_STAGE_FLOATS;
        const float* Bb = Ab + 256 * 36;
#pragma unroll
        for (int ks = 0; ks < 4; ks++) {
            const int k8 = ks * 8;
            unsigned a[4][4];
#pragma unroll
            for (int mt = 0; mt < 4; mt++) {
                const float* r0 = Ab + (wm * 64 + mt * 16 + gr) * 36;
                const float* r1 = r0 + 8 * 36;
                a[mt][0] = __float_as_uint(r0[k8 + tg]);
                a[mt][1] = __float_as_uint(r1[k8 + tg]);
                a[mt][2] = __float_as_uint(r0[k8 + 4 + tg]);
                a[mt][3] = __float_as_uint(r1[k8 + 4 + tg]);
            }
#pragma unroll
            for (int nt = 0; nt < 8; nt++) {
                const float* rb = Bb + (wn * 64 + nt * 8 + gr) * 36;
                unsigned b[2];
                b[0] = __float_as_uint(rb[k8 + tg]);
                b[1] = __float_as_uint(rb[k8 + 4 + tg]);
#pragma unroll
                for (int mt = 0; mt < 4; mt++) mma8(acc[mt][nt], a[mt], b);
            }
        }
        if (kc + 2 < 10) fill(kc + 2);
        CP_COMMIT();
    }

#pragma unroll
    for (int nt = 0; nt < 8; nt++) {
        int n = n0 + wn * 64 + nt * 8 + 2 * tg;
        float b0 = bi0[n] + bh0[n];
        float b1 = bi0[n + 1] + bh0[n + 1];
#pragma unroll
        for (int mt = 0; mt < 4; mt++) {
            int m = m0 + wm * 64 + mt * 16 + gr;
            float2 v0 = make_float2(acc[mt][nt][0] + b0, acc[mt][nt][1] + b1);
            float2 v1 = make_float2(acc[mt][nt][2] + b0, acc[mt][nt][3] + b1);
            *(float2*)(g_pre0 + (size_t)m * G4H + n) = v0;
            *(float2*)(g_pre0 + (size_t)(m + 8) * G4H + n) = v1;
        }
    }
}

// ===========================================================================
// Kernel 4: PERSISTENT layer-0 scan (round-4 proven config: 256 threads).
// ===========================================================================
__global__ __launch_bounds__(256, 1) void k_lstm0_scan(
    const float* __restrict__ h_init0, const float* __restrict__ c_init0,
    const float* __restrict__ wh0) {
    extern __shared__ float smx[];
    float* Ws = smx;                     // [4][1024][8]  g*8192 + k*8 + n
    float* Hs = smx + 4 * 1024 * 8;      // [4][256][20]  stage*5120 + m*20 + k

    const int tid = threadIdx.x, lane = tid & 31, wid = tid >> 5;
    const int tg = lane & 3, gr = lane >> 2;
    const int n0 = blockIdx.x * 8;
    const int mb = wid * 32;

#pragma unroll
    for (int rr = 0; rr < 4; rr++) {
        int r = wid * 4 + rr;                // 0..31 = g*8 + n
        int g = r >> 3, n = r & 7;
        const float* src = wh0 + (size_t)(g * H_ + n0 + n) * H_;
        float* dst = Ws + g * 8192 + n;
        for (int k4 = lane; k4 < 256; k4 += 32) {
            float4 v = *(const float4*)(src + k4 * 4);
            dst[(k4 * 4 + 0) * 8] = v.x;
            dst[(k4 * 4 + 1) * 8] = v.y;
            dst[(k4 * 4 + 2) * 8] = v.z;
            dst[(k4 * 4 + 3) * 8] = v.w;
        }
    }

    float creg[2][2][2];
#pragma unroll
    for (int mt = 0; mt < 2; mt++)
#pragma unroll
        for (int hf = 0; hf < 2; hf++) {
            int m = mb + mt * 16 + hf * 8 + gr;
            float2 cv = *(const float2*)(c_init0 + (size_t)m * H_ + n0 + 2 * tg);
            creg[mt][hf][0] = cv.x;
            creg[mt][hf][1] = cv.y;
        }

    float acc[4][2][4];
#pragma unroll
    for (int g = 0; g < 4; g++)
#pragma unroll
        for (int mt = 0; mt < 2; mt++)
#pragma unroll
            for (int r = 0; r < 4; r++) acc[g][mt][r] = 0.0f;

    __syncthreads();

    const int row_f = tid >> 2, q_f = tid & 3;

    for (int t = 0; t < T_; t++) {
        const float* hprev = (t == 0) ? h_init0 : (g_h0 + (size_t)(t - 1) * B_ * H_);
        float* hout = g_h0 + (size_t)t * B_ * H_;
        float* cout = g_c0 + (size_t)t * B_ * H_;
        const float* pt = g_pre0 + (size_t)t * B_ * G4H;

        auto fill = [&](int kc) {
            float* dst = Hs + (kc & 3) * 5120;
#pragma unroll
            for (int it = 0; it < 4; it++) {
                int row = row_f + it * 64;
                cpa16(dst + row * 20 + q_f * 4,
                      hprev + (size_t)row * H_ + kc * 16 + q_f * 4);
            }
        };

        fill(0); CP_COMMIT();
        fill(1); CP_COMMIT();
        fill(2); CP_COMMIT();

        for (int kc = 0; kc < 64; kc++) {
            cp_wait<2>();
            __syncthreads();
            const float* Hb = Hs + (kc & 3) * 5120;
#pragma unroll
            for (int ks = 0; ks < 2; ks++) {
                const int k8 = ks * 8;
                unsigned a[2][4];
#pragma unroll
                for (int mt = 0; mt < 2; mt++) {
                    const float* r0 = Hb + (mb + mt * 16 + gr) * 20;
                    const float* r1 = r0 + 8 * 20;
                    a[mt][0] = __float_as_uint(r0[k8 + tg]);
                    a[mt][1] = __float_as_uint(r1[k8 + tg]);
                    a[mt][2] = __float_as_uint(r0[k8 + 4 + tg]);
                    a[mt][3] = __float_as_uint(r1[k8 + 4 + tg]);
                }
#pragma unroll
                for (int g = 0; g < 4; g++) {
                    const float* wg = Ws + g * 8192 + (kc * 16 + k8) * 8;
                    unsigned bb[2];
                    bb[0] = __float_as_uint(wg[tg * 8 + gr]);
                    bb[1] = __float_as_uint(wg[(4 + tg) * 8 + gr]);
                    mma8(acc[g][0], a[0], bb);
                    mma8(acc[g][1], a[1], bb);
                }
            }
            if (kc + 3 < 64) fill(kc + 3);
            CP_COMMIT();
        }

#pragma unroll
        for (int mt = 0; mt < 2; mt++)
#pragma unroll
            for (int hf = 0; hf < 2; hf++) {
                int m = mb + mt * 16 + hf * 8 + gr;
                const float* p = pt + (size_t)m * G4H + n0 + 2 * tg;
                float2 Pi = *(const float2*)(p);
                float2 Pf = *(const float2*)(p + H_);
                float2 Po = *(const float2*)(p + 2 * H_);
                float2 Pg = *(const float2*)(p + 3 * H_);
                float h2[2];
#pragma unroll
                for (int cc = 0; cc < 2; cc++) {
                    int r = hf * 2 + cc;
                    float pi = acc[0][mt][r] + (cc ? Pi.y : Pi.x);
                    float pfv = acc[1][mt][r] + (cc ? Pf.y : Pf.x);
                    float po = acc[2][mt][r] + (cc ? Po.y : Po.x);
                    float pg = acc[3][mt][r] + (cc ? Pg.y : Pg.x);
                    float c = sigmoidf_(pfv) * creg[mt][hf][cc] + sigmoidf_(pi) * tanhf(pg);
                    creg[mt][hf][cc] = c;
                    h2[cc] = sigmoidf_(po) * tanhf(c);
                }
                *(float2*)(hout + (size_t)m * H_ + n0 + 2 * tg) = make_float2(h2[0], h2[1]);
                *(float2*)(cout + (size_t)m * H_ + n0 + 2 * tg) =
                    make_float2(creg[mt][hf][0], creg[mt][hf][1]);
            }
#pragma unroll
        for (int g = 0; g < 4; g++)
#pragma unroll
            for (int mt = 0; mt < 2; mt++)
#pragma unroll
                for (int r = 0; r < 4; r++) acc[g][mt][r] = 0.0f;

        __syncthreads();
        if (tid == 0) {
            __threadfence();
            atomicAdd(&g_bar, 1u);
            unsigned tgt = (unsigned)(t + 1) * SCAN_NCTA;
            while (atomicAdd(&g_bar, 0u) < tgt) __nanosleep(64);
            __threadfence();
        }
        __syncthreads();
    }
}

// ===========================================================================
// Kernel 5: layer-1 batch-parallel. BM=128, BN=256 (4 gates x 64 cols).
// 8 warps WM=2 x WN=4; per-warp mt=4, 16 cols/gate (nt=2); acc=128 regs.
// 3-stage cp.async, K=2048 (64 chunks). Grid (16, 512). LDS ratio 0.25.
// ===========================================================================
__global__ __launch_bounds__(256, 1) void k_lstm1(const float* __restrict__ wi1,
                                                  const float* __restrict__ wh1,
                                                  const float* __restrict__ bi1,
                                                  const float* __restrict__ bh1) {
    extern __shared__ float sm1[];
    // stage s: A [128][36] at sm1 + s*L1_STAGE_FLOATS, B [256][36] at +128*36

    const int m0 = blockIdx.y * 128;
    const int n0 = blockIdx.x * 64;                 // per-gate col base
    const int tid = threadIdx.x, lane = tid & 31, wid = tid >> 5;
    const int wm = wid & 1, wn = wid >> 1;          // WM=2, WN=4
    const int tg = lane & 3, gr = lane >> 2;

    float acc[4][4][2][4];
#pragma unroll
    for (int g = 0; g < 4; g++)
#pragma unroll
        for (int mt = 0; mt < 4; mt++)
#pragma unroll
            for (int nt = 0; nt < 2; nt++)
#pragma unroll
                for (int r = 0; r < 4; r++) acc[g][mt][nt][r] = 0.0f;

    auto fill = [&](int kc) {
        int s = kc % 3;
        bool second = (kc >= 32);
        int kk0 = (kc * 32) & (H_ - 1);
        float* dA = sm1 + s * L1_STAGE_FLOATS;
#pragma unroll
        for (int it = 0; it < 4; it++) {
            int idx = tid + it * 256, row = idx >> 3, q = idx & 7;   // row 0..127
            int m = m0 + row, bq = m & 255;
            int msel = second ? (m - bq + 255 - bq) : m;
            cpa16(dA + row * 36 + q * 4, g_h0 + (size_t)msel * H_ + kk0 + q * 4);
        }
        const float* W = second ? wh1 : wi1;
        float* dB = dA + 128 * 36;
#pragma unroll
        for (int it = 0; it < 8; it++) {
            int idx = tid + it * 256, row = idx >> 3, q = idx & 7;   // row 0..255
            int g = row >> 6, nn = row & 63;
            cpa16(dB + row * 36 + q * 4,
                  W + (size_t)(g * H_ + n0 + nn) * H_ + kk0 + q * 4);
        }
    };

    fill(0); CP_COMMIT();
    fill(1); CP_COMMIT();

    for (int kc = 0; kc < 64; kc++) {
        cp_wait<1>();
        __syncthreads();
        const float* Ab = sm1 + (kc % 3) * L1_STAGE_FLOATS;
        const float* Bb = Ab + 128 * 36;
#pragma unroll
        for (int ks = 0; ks < 4; ks++) {
            const int k8 = ks * 8;
            unsigned a[4][4];
#pragma unroll
            for (int mt = 0; mt < 4; mt++) {
                const float* r0 = Ab + (wm * 64 + mt * 16 + gr) * 36;
                const float* r1 = r0 + 8 * 36;
                a[mt][0] = __float_as_uint(r0[k8 + tg]);
                a[mt][1] = __float_as_uint(r1[k8 + tg]);
                a[mt][2] = __float_as_uint(r0[k8 + 4 + tg]);
                a[mt][3] = __float_as_uint(r1[k8 + 4 + tg]);
            }
#pragma unroll
            for (int g = 0; g < 4; g++) {
#pragma unroll
                for (int nt = 0; nt < 2; nt++) {
                    const float* rb = Bb + (g * 64 + wn * 16 + nt * 8 + gr) * 36;
                    unsigned b[2];
                    b[0] = __float_as_uint(rb[k8 + tg]);
                    b[1] = __float_as_uint(rb[k8 + 4 + tg]);
#pragma unroll
                    for (int mt = 0; mt < 4; mt++) mma8(acc[g][mt][nt], a[mt], b);
                }
            }
        }
        if (kc + 2 < 64) fill(kc + 2);
        CP_COMMIT();
    }

#pragma unroll
    for (int mt = 0; mt < 4; mt++)
#pragma unroll
        for (int half = 0; half < 2; half++) {
            int m = m0 + wm * 64 + mt * 16 + half * 8 + gr;
            int bq = m & 255;
            int mflip = m - bq + 255 - bq;
            const float* cp = g_c0 + (size_t)mflip * H_;
            float* hp = g_h1 + (size_t)m * H_;
#pragma unroll
            for (int nt = 0; nt < 2; nt++)
#pragma unroll
                for (int cc = 0; cc < 2; cc++) {
                    int nn = n0 + wn * 16 + nt * 8 + 2 * tg + cc;
                    int r = half * 2 + cc;
                    float pi = acc[0][mt][nt][r] + bi1[nn] + bh1[nn];
                    float pf = acc[1][mt][nt][r] + bi1[H_ + nn] + bh1[H_ + nn];
                    float po = acc[2][mt][nt][r] + bi1[2 * H_ + nn] + bh1[2 * H_ + nn];
                    float pg = acc[3][mt][nt][r] + bi1[3 * H_ + nn] + bh1[3 * H_ + nn];
                    float c = sigmoidf_(pf) * cp[nn] + sigmoidf_(pi) * tanhf(pg);
                    hp[nn] = sigmoidf_(po) * tanhf(c);
                }
        }
}

// ===========================================================================
// Kernel 6: decode. out[m, c] = [h0[m] | h1[m]] . dec_w[c] + dec_b[c]
// ===========================================================================
__global__ __launch_bounds__(256) void k_decode(const float* __restrict__ dec_w,
                                                const float* __restrict__ dec_b,
                                                float* __restrict__ out) {
    int gwarp = (blockIdx.x * blockDim.x + threadIdx.x) >> 5;
    int lane = threadIdx.x & 31;
    if (gwarp >= M_) return;
    const float* h0r = g_h0 + (size_t)gwarp * H_;
    const float* h1r = g_h1 + (size_t)gwarp * H_;

    float acc[C_];
#pragma unroll
    for (int c = 0; c < C_; c++) acc[c] = 0.0f;

    for (int k = lane * 4; k < H_; k += 128) {
        float4 v0 = *(const float4*)(h0r + k);
        float4 v1 = *(const float4*)(h1r + k);
#pragma unroll
        for (int c = 0; c < C_; c++) {
            const float* w = dec_w + (size_t)c * 2 * H_;
            float4 w0 = *(const float4*)(w + k);
            float4 w1 = *(const float4*)(w + H_ + k);
            acc[c] += v0.x * w0.x + v0.y * w0.y + v0.z * w0.z + v0.w * w0.w
                    + v1.x * w1.x + v1.y * w1.y + v1.z * w1.z + v1.w * w1.w;
        }
    }
#pragma unroll
    for (int c = 0; c < C_; c++) {
#pragma unroll
        for (int off = 16; off > 0; off >>= 1)
            acc[c] += __shfl_down_sync(0xFFFFFFFFu, acc[c], off);
    }
    if (lane == 0) {
#pragma unroll
        for (int c = 0; c < C_; c++)
            out[(size_t)gwarp * C_ + c] = acc[c] + dec_b[c];
    }
}

// ===========================================================================
// Launch
// ===========================================================================
extern "C" void kernel_launch(void* const* d_in, const int* in_sizes, int n_in,
                              void* d_out, int out_size) {
    const int*   tokens = (const int*)d_in[0];
    const float* casing = (const float*)d_in[1];
    const float* pos    = (const float*)d_in[2];
    const float* emb    = (const float*)d_in[3];
    const float* wi0    = (const float*)d_in[4];
    const float* bi0    = (const float*)d_in[5];
    const float* wh0    = (const float*)d_in[6];
    const float* bh0    = (const float*)d_in[7];
    const float* wi1    = (const float*)d_in[8];
    const float* bi1    = (const float*)d_in[9];
    const float* wh1    = (const float*)d_in[10];
    const float* bh1    = (const float*)d_in[11];
    const float* dec_w  = (const float*)d_in[12];
    const float* dec_b  = (const float*)d_in[13];
    const float* h_init = (const float*)d_in[14];
    const float* c_init = (const float*)d_in[15];
    float* out = (float*)d_out;

    (void)in_sizes; (void)n_in; (void)out_size;

    cudaFuncSetAttribute(k_lstm0_scan, cudaFuncAttributeMaxDynamicSharedMemorySize,
                         SCAN_SMEM);
    cudaFuncSetAttribute(k_lstm1, cudaFuncAttributeMaxDynamicSharedMemorySize,
                         L1_SMEM);
    cudaFuncSetAttribute(k_gemm_pre0, cudaFuncAttributeMaxDynamicSharedMemorySize,
                         P0_SMEM);

    k_reset<<<1, 1>>>();
    k_build_x<<<M_, 256>>>(tokens, casing, pos, emb);
    k_pad_wi0<<<G4H, 256>>>(wi0);
    k_gemm_pre0<<<dim3(G4H / 128, M_ / 256), 256, P0_SMEM>>>(bi0, bh0);
    k_lstm0_scan<<<SCAN_NCTA, 256, SCAN_SMEM>>>(h_init, c_init, wh0);
    k_lstm1<<<dim3(H_ / 64, M_ / 128), 256, L1_SMEM>>>(wi1, wh1, bi1, bh1);
    k_decode<<<(M_ * 32) / 256, 256>>>(dec_w, dec_b, out);
}